// round 5
// baseline (speedup 1.0000x reference)
#include <cuda_runtime.h>
#include <math.h>

#define IMG     512
#define NVIEW   360
#define NQ      8            // row-slices per view
#define RQ      (IMG / NQ)   // 64 rows per CTA
#define NSTAGE  (RQ / 2)     // 2 rows per stage
#define PW      516          // pair-row width (entries 0..514 valid, 515 pad)
#define OUTN    (2 * IMG * NVIEW)

// Pair image, batch-interleaved, both orientations, zeros baked into borders:
//   g_pair_row[p*PW+i] = (b0[y=p-1][x=i-1], b1[..], b0[y=p-1][x=i],   b1[..])
//   g_pair_col[p*PW+i] = (b0[y=i-1][x=p-1], b1[..], b0[y=i  ][x=p-1], b1[..])
// One float4 = both bilinear x-taps (or y-taps) for BOTH batches.
__device__ float4 g_pair_row[514 * PW];
__device__ float4 g_pair_col[514 * PW];
// Per-view params: (a, bcoef, sA, sB); P = a*hr + (sA*wr + 255.5), Q = bcoef*hr + (sB*wr + 255.5)
__device__ float4 g_vp[NVIEW];
__device__ int    g_vmode[NVIEW];

__device__ __forceinline__ float2 pix(const float* __restrict__ x, int y, int xx) {
    float2 f = make_float2(0.f, 0.f);
    if ((unsigned)y < 512u && (unsigned)xx < 512u) {
        f.x = x[y * IMG + xx];
        f.y = x[IMG * IMG + y * IMG + xx];
    }
    return f;
}

__global__ void prep_kernel(const float* __restrict__ x, float* __restrict__ out) {
    int idx = blockIdx.x * blockDim.x + threadIdx.x;

    if (idx < NVIEW) {
        double ang = -M_PI * (double)(idx + 1) / (double)NVIEW - M_PI;
        float c = (float)cos(ang);
        float s = (float)sin(ang);
        if (fabsf(c) >= fabsf(s)) {          // row mode: stepped coord P = iy
            g_vp[idx] = make_float4(c, -s, s, c);
            g_vmode[idx] = 0;
        } else {                             // col mode: stepped coord P = ix
            g_vp[idx] = make_float4(-s, c, c, s);
            g_vmode[idx] = 1;
        }
    }

    if (idx < OUTN) out[idx] = 0.0f;         // fp_kernel accumulates atomically

    const int N1 = 514 * PW;
    if (idx < 2 * N1) {
        int o   = idx / N1;
        int rem = idx - o * N1;
        int p   = rem / PW;                  // padded major index (0..513)
        int i   = rem - p * PW;              // pair index (0..515)
        float4 f;
        if (o == 0) {                        // row orientation: p=py, i over x
            float2 t0 = pix(x, p - 1, i - 1);
            float2 t1 = pix(x, p - 1, i);
            f = make_float4(t0.x, t0.y, t1.x, t1.y);
            g_pair_row[p * PW + i] = f;
        } else {                             // col orientation: p=px, i over y
            float2 t0 = pix(x, i - 1, p - 1);
            float2 t1 = pix(x, i,     p - 1);
            f = make_float4(t0.x, t0.y, t1.x, t1.y);
            g_pair_col[p * PW + i] = f;
        }
    }
}

__global__ __launch_bounds__(512) void fp_kernel(float* __restrict__ out) {
    __shared__ float4 sp[2][2][PW];

    int v = blockIdx.x;            // view
    int q = blockIdx.y;            // row slice
    int w = threadIdx.x;           // detector bin
    int r0 = q * RQ;

    float4 vp = g_vp[v];
    const float4* __restrict__ G = g_vmode[v] ? g_pair_col : g_pair_row;

    float a  = vp.x;
    float bc = vp.y;
    float wr = (float)w - 255.5f;
    float A  = fmaf(vp.z, wr, 255.5f);
    float B  = fmaf(vp.w, wr, 255.5f);
    float inv_a = 1.0f / a;

    float acc0 = 0.f, acc1 = 0.f;

    // preload stage 0: image rows r0, r0+1 -> padded rows r0+1, r0+2
    {
        const float4* s0 = G + (size_t)(r0 + 1) * PW;
        const float4* s1 = G + (size_t)(r0 + 2) * PW;
        sp[0][0][w] = s0[w];
        sp[0][1][w] = s1[w];
        if (w < 2) { sp[0][0][512 + w] = s0[512 + w]; sp[0][1][512 + w] = s1[512 + w]; }
    }

    for (int st = 0; st < NSTAGE; st++) {
        __syncthreads();
        if (st + 1 < NSTAGE) {
            int nb = (st + 1) & 1;
            const float4* s0 = G + (size_t)(r0 + 2 * st + 3) * PW;
            const float4* s1 = G + (size_t)(r0 + 2 * st + 4) * PW;
            sp[nb][0][w] = s0[w];
            sp[nb][1][w] = s1[w];
            if (w < 2) { sp[nb][0][512 + w] = s0[512 + w]; sp[nb][1][512 + w] = s1[512 + w]; }
        }

        #pragma unroll
        for (int j = 0; j < 2; j++) {
            int r = r0 + 2 * st + j;
            const float4* row = sp[st & 1][j];

            float rf = (float)r;
            // h solving P(h)=r: hc = (r-A)/a + 255.5. Open support |P-r|<1 has
            // length 2/|a| <= 2.829; 3 candidates from ceil(hc-1.4146) cover it.
            float hc = fmaf(rf - A, inv_a, 255.5f);
            float hb = ceilf(hc - 1.4146f);
            int   h0 = (int)hb;

            float P = fmaf(a,  hb - 255.5f, A);
            float Q = fmaf(bc, hb - 255.5f, B);

            #pragma unroll
            for (int k = 0; k < 3; k++) {
                float wp = 1.0f - fabsf(P - rf);
                wp = fmaxf(wp, 0.0f);
                if ((unsigned)(h0 + k) >= 512u) wp = 0.0f;

                float Qc = fminf(fmaxf(Q, -1.0f), 512.0f);  // clamp lands on zero pads
                float q0 = floorf(Qc);
                float wq = Qc - q0;
                int   px = (int)q0 + 1;                     // 0..513

                float4 t = row[px];                         // one LDS.128: both taps, both batches
                acc0 = fmaf(wp, fmaf(wq, t.z - t.x, t.x), acc0);
                acc1 = fmaf(wp, fmaf(wq, t.w - t.y, t.y), acc1);

                P += a;
                Q += bc;
            }
        }
    }

    atomicAdd(&out[w * NVIEW + v],              acc0 * 0.5f);
    atomicAdd(&out[IMG * NVIEW + w * NVIEW + v], acc1 * 0.5f);
}

extern "C" void kernel_launch(void* const* d_in, const int* in_sizes, int n_in,
                              void* d_out, int out_size) {
    const float* x = (const float*)d_in[0];
    float* out = (float*)d_out;

    int nprep = 2 * 514 * PW;
    prep_kernel<<<(nprep + 255) / 256, 256>>>(x, out);

    dim3 grid(NVIEW, NQ);
    fp_kernel<<<grid, 512>>>(out);
}

// round 6
// speedup vs baseline: 1.2195x; 1.2195x over previous
#include <cuda_runtime.h>
#include <cuda_fp16.h>
#include <math.h>

#define IMG     512
#define NVIEW   360
#define NQ      8            // row-slices per view
#define RQ      (IMG / NQ)   // 64 rows per CTA
#define NSTAGE  (RQ / 2)     // 2 rows per stage
#define PW      516          // pair-row width (entries 0..513 used)
#define OUTN    (2 * IMG * NVIEW)

// fp16 dup-pair image, batch-interleaved, both orientations, zeros baked in:
// entry i of padded row p = { half2(b0,b1) at pixel i-1 , half2(b0,b1) at pixel i }
// One 8B LDS.64 = both bilinear taps for BOTH batches.
__device__ uint2 g_pair_row[514 * PW];
__device__ uint2 g_pair_col[514 * PW];
// Per-view params: (a, bcoef, sA, sB); P = a*hr + (sA*wr+255.5), Q = bc*hr + (sB*wr+255.5)
__device__ float4 g_vp[NVIEW];
__device__ int    g_vmode[NVIEW];

__device__ __forceinline__ float2 pix(const float* __restrict__ x, int y, int xx) {
    float2 f = make_float2(0.f, 0.f);
    if ((unsigned)y < 512u && (unsigned)xx < 512u) {
        f.x = x[y * IMG + xx];
        f.y = x[IMG * IMG + y * IMG + xx];
    }
    return f;
}

__global__ void prep_kernel(const float* __restrict__ x, float* __restrict__ out) {
    int idx = blockIdx.x * blockDim.x + threadIdx.x;

    if (idx < NVIEW) {
        double ang = -M_PI * (double)(idx + 1) / (double)NVIEW - M_PI;
        float c = (float)cos(ang);
        float s = (float)sin(ang);
        if (fabsf(c) >= fabsf(s)) g_vp[idx] = make_float4(c, -s, s, c),  g_vmode[idx] = 0;
        else                      g_vp[idx] = make_float4(-s, c, c, s),  g_vmode[idx] = 1;
    }

    if (idx < OUTN) out[idx] = 0.0f;   // fp_kernel accumulates atomically

    const int N1 = 514 * PW;
    if (idx < 2 * N1) {
        int o   = idx / N1;
        int rem = idx - o * N1;
        int p   = rem / PW;
        int i   = rem - p * PW;
        float2 t0, t1;
        if (o == 0) { t0 = pix(x, p - 1, i - 1); t1 = pix(x, p - 1, i); }
        else        { t0 = pix(x, i - 1, p - 1); t1 = pix(x, i,     p - 1); }
        __half2 h0 = __float22half2_rn(t0);
        __half2 h1 = __float22half2_rn(t1);
        uint2 e;
        e.x = *reinterpret_cast<unsigned*>(&h0);
        e.y = *reinterpret_cast<unsigned*>(&h1);
        if (o == 0) g_pair_row[p * PW + i] = e;
        else        g_pair_col[p * PW + i] = e;
    }
}

template <bool CHK>
__device__ __forceinline__ void cand(const uint2* __restrict__ row,
                                     float dk, float Q, int hk, float absa,
                                     float& acc0, float& acc1) {
    float wp = fmaf(-absa, fabsf(dk), 1.0f);    // == 1 - |P - r|
    wp = fmaxf(wp, 0.0f);
    if (CHK) { if ((unsigned)hk >= 512u) wp = 0.0f; }

    float Qc = fminf(fmaxf(Q, -1.0f), 512.0f);  // clamp lands on zero pads
    float q0 = floorf(Qc);
    float wq = Qc - q0;
    int   px = (int)q0 + 1;                     // 0..513

    uint2 e = row[px];
    __half2 lo = *reinterpret_cast<const __half2*>(&e.x);
    __half2 hi = *reinterpret_cast<const __half2*>(&e.y);
    __half2 m  = __hfma2(__float2half2_rn(wq), __hsub2(hi, lo), lo);
    float2 mf  = __half22float2(m);
    acc0 = fmaf(wp, mf.x, acc0);
    acc1 = fmaf(wp, mf.y, acc1);
}

__global__ __launch_bounds__(512) void fp_kernel(float* __restrict__ out) {
    __shared__ uint2 sp[2][2][PW];

    int v = blockIdx.x;
    int q = blockIdx.y;
    int w = threadIdx.x;
    int r0 = q * RQ;

    float4 vp = g_vp[v];
    const uint2* __restrict__ G = g_vmode[v] ? g_pair_col : g_pair_row;

    float a    = vp.x;
    float bc   = vp.y;
    float absa = fabsf(a);
    float wr = (float)w - 255.5f;
    float A  = fmaf(vp.z, wr, 255.5f);
    float B  = fmaf(vp.w, wr, 255.5f);
    float inv_a = 1.0f / a;

    float acc0 = 0.f, acc1 = 0.f;

    // preload stage 0 (image rows r0, r0+1 -> padded rows r0+1, r0+2)
    {
        const uint2* s0 = G + (size_t)(r0 + 1) * PW;
        const uint2* s1 = G + (size_t)(r0 + 2) * PW;
        sp[0][0][w] = s0[w];
        sp[0][1][w] = s1[w];
        if (w < 2) { sp[0][0][512 + w] = s0[512 + w]; sp[0][1][512 + w] = s1[512 + w]; }
    }

    for (int st = 0; st < NSTAGE; st++) {
        __syncthreads();
        if (st + 1 < NSTAGE) {
            int nb = (st + 1) & 1;
            const uint2* s0 = G + (size_t)(r0 + 2 * st + 3) * PW;
            const uint2* s1 = G + (size_t)(r0 + 2 * st + 4) * PW;
            sp[nb][0][w] = s0[w];
            sp[nb][1][w] = s1[w];
            if (w < 2) { sp[nb][0][512 + w] = s0[512 + w]; sp[nb][1][512 + w] = s1[512 + w]; }
        }

        #pragma unroll
        for (int j = 0; j < 2; j++) {
            int r = r0 + 2 * st + j;
            const uint2* row = sp[st & 1][j];

            float rf = (float)r;
            // hc solves P(h)=r in h-index space; open support spans < 2*sqrt(2),
            // 3 candidates from hb = ceil(hc - 1.4146) provably cover it.
            float hc = fmaf(rf - A, inv_a, 255.5f);
            float hb = ceilf(hc - 1.4146f);
            int   h0 = (int)hb;
            float d  = hb - hc;
            float Q  = fmaf(bc, hb - 255.5f, B);

            if (h0 >= 0 && h0 <= 509) {   // all three h valid: skip range tests
                cand<false>(row, d,        Q,            h0,     absa, acc0, acc1);
                cand<false>(row, d + 1.f,  Q + bc,       h0 + 1, absa, acc0, acc1);
                cand<false>(row, d + 2.f,  Q + 2.f * bc, h0 + 2, absa, acc0, acc1);
            } else {
                cand<true> (row, d,        Q,            h0,     absa, acc0, acc1);
                cand<true> (row, d + 1.f,  Q + bc,       h0 + 1, absa, acc0, acc1);
                cand<true> (row, d + 2.f,  Q + 2.f * bc, h0 + 2, absa, acc0, acc1);
            }
        }
    }

    atomicAdd(&out[w * NVIEW + v],               acc0 * 0.5f);
    atomicAdd(&out[IMG * NVIEW + w * NVIEW + v], acc1 * 0.5f);
}

extern "C" void kernel_launch(void* const* d_in, const int* in_sizes, int n_in,
                              void* d_out, int out_size) {
    const float* x = (const float*)d_in[0];
    float* out = (float*)d_out;

    int nprep = 2 * 514 * PW;
    prep_kernel<<<(nprep + 255) / 256, 256>>>(x, out);

    dim3 grid(NVIEW, NQ);
    fp_kernel<<<grid, 512>>>(out);
}

// round 8
// speedup vs baseline: 1.4699x; 1.2053x over previous
#include <cuda_runtime.h>
#include <cuda_fp16.h>
#include <math.h>

#define IMG     512
#define NVIEW   360
#define NPAIR   180          // view pairs (v, v+180): angles differ by exactly pi/2
#define NQ      8            // row-slices per view-pair
#define RQ      (IMG / NQ)   // 64 rows per CTA
#define NSTAGE  (RQ / 2)
#define PW      516
#define N1      (514 * PW)
#define OUTN    (2 * IMG * NVIEW)

// fp16 dup-pair images (batch-interleaved), zeros baked into borders.
// Entry i of padded major-line p = { half2(b0,b1)@pixel i-1 , half2(b0,b1)@pixel i }.
// Four variants: row/col orientation x {normal I, 90deg-rotated J[r][c]=I[511-c][r]}.
__device__ uint2 g_pair_row [N1];
__device__ uint2 g_pair_col [N1];
__device__ uint2 g_pair_rowJ[N1];
__device__ uint2 g_pair_colJ[N1];
__device__ float4 g_vp[NVIEW];
__device__ int    g_vmode[NVIEW];

__device__ __forceinline__ unsigned h2pix(const float* __restrict__ x, int y, int xx) {
    float2 f = make_float2(0.f, 0.f);
    if ((unsigned)y < 512u && (unsigned)xx < 512u) {
        f.x = x[y * IMG + xx];
        f.y = x[IMG * IMG + y * IMG + xx];
    }
    __half2 h = __float22half2_rn(f);
    return *reinterpret_cast<unsigned*>(&h);
}

__global__ void prep_kernel(const float* __restrict__ x, float* __restrict__ out) {
    int idx = blockIdx.x * blockDim.x + threadIdx.x;

    if (idx < NVIEW) {
        double ang = -M_PI * (double)(idx + 1) / (double)NVIEW - M_PI;
        float c = (float)cos(ang);
        float s = (float)sin(ang);
        if (fabsf(c) >= fabsf(s)) g_vp[idx] = make_float4(c, -s, s, c),  g_vmode[idx] = 0;
        else                      g_vp[idx] = make_float4(-s, c, c, s),  g_vmode[idx] = 1;
    }

    if (idx < OUTN) out[idx] = 0.0f;   // fp_kernel accumulates atomically

    if (idx < N1) {
        int p = idx / PW;
        int i = idx - p * PW;
        // normal image I: row layout (line p = image row p-1, i over x),
        //                 col layout (line p = image col p-1, i over y)
        g_pair_row [idx] = make_uint2(h2pix(x, p - 1, i - 1),  h2pix(x, p - 1, i));
        g_pair_col [idx] = make_uint2(h2pix(x, i - 1, p - 1),  h2pix(x, i,     p - 1));
        // rotated image J[r][c] = I[511-c][r]:
        //   rowJ line p, entry i = ( J[p-1][i-1], J[p-1][i] ) = ( I[512-i][p-1], I[511-i][p-1] )
        //   colJ line p, entry i = ( J[i-1][p-1], J[i][p-1] ) = ( I[512-p][i-1], I[512-p][i] )
        g_pair_rowJ[idx] = make_uint2(h2pix(x, 512 - i, p - 1), h2pix(x, 511 - i, p - 1));
        g_pair_colJ[idx] = make_uint2(h2pix(x, 512 - p, i - 1), h2pix(x, 512 - p, i));
    }
}

__device__ __forceinline__ void cand2(const uint2* __restrict__ row,
                                      const uint2* __restrict__ rowJ,
                                      float wp, float Q,
                                      float& a0, float& a1, float& a2, float& a3) {
    float Qc = fminf(fmaxf(Q, -1.0f), 512.0f);   // clamp lands on zero pads
    float q0 = floorf(Qc);
    float wq = Qc - q0;
    int   px = (int)q0 + 1;                      // 0..513
    __half2 wqh = __float2half2_rn(wq);

    uint2 e  = row[px];
    uint2 eJ = rowJ[px];
    __half2 m  = __hfma2(wqh, __hsub2(*(const __half2*)&e.y,  *(const __half2*)&e.x),
                         *(const __half2*)&e.x);
    __half2 mJ = __hfma2(wqh, __hsub2(*(const __half2*)&eJ.y, *(const __half2*)&eJ.x),
                         *(const __half2*)&eJ.x);
    float2 mf  = __half22float2(m);
    float2 mfJ = __half22float2(mJ);
    a0 = fmaf(wp, mf.x,  a0);
    a1 = fmaf(wp, mf.y,  a1);
    a2 = fmaf(wp, mfJ.x, a2);
    a3 = fmaf(wp, mfJ.y, a3);
}

__global__ __launch_bounds__(512) void fp_kernel(float* __restrict__ out) {
    __shared__ uint2 sp[2][2][2][PW];   // [buf][row-in-stage][img][entry]

    int v = blockIdx.x;            // primary view; pair view = v + 180
    int q = blockIdx.y;
    int w = threadIdx.x;
    int r0 = q * RQ;

    float4 vp = g_vp[v];
    int mode = g_vmode[v];
    const uint2* __restrict__ G  = mode ? g_pair_col  : g_pair_row;
    const uint2* __restrict__ GJ = mode ? g_pair_colJ : g_pair_rowJ;

    float a    = vp.x;
    float bc   = vp.y;
    float absa = fabsf(a);
    float wr = (float)w - 255.5f;
    float A  = fmaf(vp.z, wr, 255.5f);
    float B  = fmaf(vp.w, wr, 255.5f);
    float inv_a = 1.0f / a;

    float a0 = 0.f, a1 = 0.f, a2 = 0.f, a3 = 0.f;

    // preload stage 0 (image rows r0, r0+1 -> padded lines r0+1, r0+2)
    {
        const uint2* s0 = G  + (size_t)(r0 + 1) * PW;
        const uint2* s1 = G  + (size_t)(r0 + 2) * PW;
        const uint2* t0 = GJ + (size_t)(r0 + 1) * PW;
        const uint2* t1 = GJ + (size_t)(r0 + 2) * PW;
        sp[0][0][0][w] = s0[w];  sp[0][1][0][w] = s1[w];
        sp[0][0][1][w] = t0[w];  sp[0][1][1][w] = t1[w];
        if (w < 2) {
            sp[0][0][0][512 + w] = s0[512 + w];  sp[0][1][0][512 + w] = s1[512 + w];
            sp[0][0][1][512 + w] = t0[512 + w];  sp[0][1][1][512 + w] = t1[512 + w];
        }
    }

    for (int st = 0; st < NSTAGE; st++) {
        __syncthreads();
        if (st + 1 < NSTAGE) {
            int nb = (st + 1) & 1;
            const uint2* s0 = G  + (size_t)(r0 + 2 * st + 3) * PW;
            const uint2* s1 = G  + (size_t)(r0 + 2 * st + 4) * PW;
            const uint2* t0 = GJ + (size_t)(r0 + 2 * st + 3) * PW;
            const uint2* t1 = GJ + (size_t)(r0 + 2 * st + 4) * PW;
            sp[nb][0][0][w] = s0[w];  sp[nb][1][0][w] = s1[w];
            sp[nb][0][1][w] = t0[w];  sp[nb][1][1][w] = t1[w];
            if (w < 2) {
                sp[nb][0][0][512 + w] = s0[512 + w];  sp[nb][1][0][512 + w] = s1[512 + w];
                sp[nb][0][1][512 + w] = t0[512 + w];  sp[nb][1][1][512 + w] = t1[512 + w];
            }
        }

        #pragma unroll
        for (int j = 0; j < 2; j++) {
            int r = r0 + 2 * st + j;
            const uint2* row  = sp[st & 1][j][0];
            const uint2* rowJ = sp[st & 1][j][1];

            float rf = (float)r;
            // hc solves P(h)=r; open support spans < 2*sqrt(2); 3 candidates
            // from hb = ceil(hc - 1.4146) provably cover it.
            float hc = fmaf(rf - A, inv_a, 255.5f);
            float hb = ceilf(hc - 1.4146f);
            int   h0 = (int)hb;
            float d  = hb - hc;                   // in (-1.4146, -0.4146]
            float Q  = fmaf(bc, hb - 255.5f, B);

            float wp0 = fmaxf(fmaf( absa, d,               1.0f), 0.0f);  // d < 0
            float wp1 = fmaxf(fmaf(-absa, fabsf(d + 1.0f), 1.0f), 0.0f);
            float wp2 = fmaxf(fmaf(-absa, d + 2.0f,        1.0f), 0.0f);  // d+2 > 0

            if ((unsigned)h0 > 509u) {            // rare edge rows
                if ((unsigned)h0       >= 512u) wp0 = 0.0f;
                if ((unsigned)(h0 + 1) >= 512u) wp1 = 0.0f;
                if ((unsigned)(h0 + 2) >= 512u) wp2 = 0.0f;
            }

            cand2(row, rowJ, wp0, Q,             a0, a1, a2, a3);
            cand2(row, rowJ, wp1, Q + bc,        a0, a1, a2, a3);
            cand2(row, rowJ, wp2, Q + 2.0f * bc, a0, a1, a2, a3);
        }
    }

    int v2 = v + NPAIR;
    atomicAdd(&out[w * NVIEW + v],                a0 * 0.5f);
    atomicAdd(&out[IMG * NVIEW + w * NVIEW + v],  a1 * 0.5f);
    atomicAdd(&out[w * NVIEW + v2],               a2 * 0.5f);
    atomicAdd(&out[IMG * NVIEW + w * NVIEW + v2], a3 * 0.5f);
}

extern "C" void kernel_launch(void* const* d_in, const int* in_sizes, int n_in,
                              void* d_out, int out_size) {
    const float* x = (const float*)d_in[0];
    float* out = (float*)d_out;

    int nprep = OUTN;   // >= N1 and >= NVIEW
    prep_kernel<<<(nprep + 255) / 256, 256>>>(x, out);

    dim3 grid(NPAIR, NQ);
    fp_kernel<<<grid, 512>>>(out);
}

// round 9
// speedup vs baseline: 1.6739x; 1.1388x over previous
#include <cuda_runtime.h>
#include <cuda_fp16.h>
#include <math.h>

#define IMG     512
#define NVIEW   360
#define NPAIR   180          // view pairs (v, v+180): angles differ by exactly pi/2
#define NQ      8
#define RQ      (IMG / NQ)   // 64 rows per CTA
#define NSTAGE  (RQ / 2)
#define PW      516          // gmem line stride (entries 0..513 valid)
#define SPW     514          // smem line width
#define N1      (514 * PW)
#define OUTN    (2 * IMG * NVIEW)

// Interleaved fp16 dup-pair images, batch-interleaved, zeros baked into borders.
// Entry i of padded line p = ( I_lo, I_hi, J_lo, J_hi ) where each is half2(b0,b1),
// lo = pixel i-1, hi = pixel i, and J[r][c] = I[511-c][r] (90-deg rotation pairs
// view v with view v+180 whose angle differs by exactly pi/2).
__device__ uint4 g_ir[N1];   // row orientation
__device__ uint4 g_ic[N1];   // col orientation
__device__ float4 g_vp[NVIEW];
__device__ int    g_vmode[NVIEW];

__device__ __forceinline__ unsigned h2pix(const float* __restrict__ x, int y, int xx) {
    float2 f = make_float2(0.f, 0.f);
    if ((unsigned)y < 512u && (unsigned)xx < 512u) {
        f.x = x[y * IMG + xx];
        f.y = x[IMG * IMG + y * IMG + xx];
    }
    __half2 h = __float22half2_rn(f);
    return *reinterpret_cast<unsigned*>(&h);
}

__global__ void prep_kernel(const float* __restrict__ x, float* __restrict__ out) {
    int idx = blockIdx.x * blockDim.x + threadIdx.x;

    if (idx < NVIEW) {
        double ang = -M_PI * (double)(idx + 1) / (double)NVIEW - M_PI;
        float c = (float)cos(ang);
        float s = (float)sin(ang);
        if (fabsf(c) >= fabsf(s)) g_vp[idx] = make_float4(c, -s, s, c),  g_vmode[idx] = 0;
        else                      g_vp[idx] = make_float4(-s, c, c, s),  g_vmode[idx] = 1;
    }

    if (idx < OUTN) out[idx] = 0.0f;   // fp_kernel accumulates atomically

    if (idx < N1) {
        int p = idx / PW;
        int i = idx - p * PW;
        // row orientation: I part = image row p-1; J part = J row p-1 = I[512-i..][p-1]
        g_ir[idx] = make_uint4(h2pix(x, p - 1,   i - 1), h2pix(x, p - 1,   i),
                               h2pix(x, 512 - i, p - 1), h2pix(x, 511 - i, p - 1));
        // col orientation: I part = image col p-1; J part = J col p-1 = I[512-p][i-1..i]
        g_ic[idx] = make_uint4(h2pix(x, i - 1,   p - 1), h2pix(x, i,       p - 1),
                               h2pix(x, 512 - p, i - 1), h2pix(x, 512 - p, i));
    }
}

__device__ __forceinline__ void cand(const uint4* __restrict__ rowp,  // tile + 1
                                     float wp, float Q,
                                     float& a0, float& a1, float& a2, float& a3) {
    float Qc = fminf(fmaxf(Q, -1.0f), 512.0f);   // clamp lands on zero pads
    float q0 = floorf(Qc);
    float wq = Qc - q0;
    uint4 e = rowp[(int)q0];                     // one LDS.128: 4 pixels, both imgs+batches
    __half2 wqh = __float2half2_rn(wq);
    __half2 mI = __hfma2(wqh, __hsub2(*(const __half2*)&e.y, *(const __half2*)&e.x),
                         *(const __half2*)&e.x);
    __half2 mJ = __hfma2(wqh, __hsub2(*(const __half2*)&e.w, *(const __half2*)&e.z),
                         *(const __half2*)&e.z);
    float2 fI = __half22float2(mI);
    float2 fJ = __half22float2(mJ);
    a0 = fmaf(wp, fI.x, a0);
    a1 = fmaf(wp, fI.y, a1);
    a2 = fmaf(wp, fJ.x, a2);
    a3 = fmaf(wp, fJ.y, a3);
}

__global__ __launch_bounds__(512) void fp_kernel(float* __restrict__ out) {
    __shared__ uint4 sp[2][2][SPW];   // [buf][row-in-stage][entry], 32.9 KB

    int v = blockIdx.x;               // primary view; pair view = v + 180
    int q = blockIdx.y;
    int w = threadIdx.x;
    int r0 = q * RQ;

    float4 vp = g_vp[v];
    const uint4* __restrict__ G = g_vmode[v] ? g_ic : g_ir;

    float a    = vp.x;
    float bc   = vp.y;
    float absa = fabsf(a);
    float c2   = 1.0f - 2.0f * absa;            // for wp2
    float wr   = (float)w - 255.5f;
    float A    = fmaf(vp.z, wr, 255.5f);
    float B    = fmaf(vp.w, wr, 255.5f);
    float Bp   = fmaf(-255.5f, bc, B);          // Q = bc*hb + Bp
    float inv_a = 1.0f / a;

    float a0 = 0.f, a1 = 0.f, a2 = 0.f, a3 = 0.f;

    // hc at r = r0, advanced incrementally (drift << window margin)
    float hcv = fmaf((float)r0 - A, inv_a, 255.5f);

    // preload stage 0 (image rows r0, r0+1 -> padded lines r0+1, r0+2)
    {
        const uint4* s0 = G + (size_t)(r0 + 1) * PW;
        const uint4* s1 = G + (size_t)(r0 + 2) * PW;
        sp[0][0][w] = s0[w];
        sp[0][1][w] = s1[w];
        if (w < 2) { sp[0][0][512 + w] = s0[512 + w]; sp[0][1][512 + w] = s1[512 + w]; }
    }

    for (int st = 0; st < NSTAGE; st++) {
        __syncthreads();
        if (st + 1 < NSTAGE) {
            int nb = (st + 1) & 1;
            const uint4* s0 = G + (size_t)(r0 + 2 * st + 3) * PW;
            const uint4* s1 = G + (size_t)(r0 + 2 * st + 4) * PW;
            sp[nb][0][w] = s0[w];
            sp[nb][1][w] = s1[w];
            if (w < 2) { sp[nb][0][512 + w] = s0[512 + w]; sp[nb][1][512 + w] = s1[512 + w]; }
        }

        #pragma unroll
        for (int j = 0; j < 2; j++) {
            const uint4* rowp = &sp[st & 1][j][1];   // +1: index by (int)floor(Qc) in [-1,512]

            // hc solves P(h)=r; open support spans < 2*sqrt(2); 3 candidates
            // from hb = ceil(hc - 1.4146) provably cover it.
            float hb = ceilf(hcv - 1.4146f);
            int   h0 = (int)hb;
            float d  = hb - hcv;                  // in (-1.4146, -0.4146]
            float Q  = fmaf(bc, hb, Bp);

            float wp0 = fmaxf(fmaf( absa, d,               1.0f), 0.0f);  // d < 0
            float wp1 = fmaxf(fmaf(-absa, fabsf(d + 1.0f), 1.0f), 0.0f);
            float wp2 = fmaxf(fmaf(-absa, d,               c2),   0.0f);  // = 1-|a|(d+2)

            if ((unsigned)h0 > 509u) {            // rare edge rows
                if ((unsigned)h0       >= 512u) wp0 = 0.0f;
                if ((unsigned)(h0 + 1) >= 512u) wp1 = 0.0f;
                if ((unsigned)(h0 + 2) >= 512u) wp2 = 0.0f;
            }

            cand(rowp, wp0, Q,             a0, a1, a2, a3);
            cand(rowp, wp1, Q + bc,        a0, a1, a2, a3);
            cand(rowp, wp2, Q + 2.0f * bc, a0, a1, a2, a3);

            hcv += inv_a;
        }
    }

    int v2 = v + NPAIR;
    atomicAdd(&out[w * NVIEW + v],                a0 * 0.5f);
    atomicAdd(&out[IMG * NVIEW + w * NVIEW + v],  a1 * 0.5f);
    atomicAdd(&out[w * NVIEW + v2],               a2 * 0.5f);
    atomicAdd(&out[IMG * NVIEW + w * NVIEW + v2], a3 * 0.5f);
}

extern "C" void kernel_launch(void* const* d_in, const int* in_sizes, int n_in,
                              void* d_out, int out_size) {
    const float* x = (const float*)d_in[0];
    float* out = (float*)d_out;

    int nprep = OUTN;   // >= N1 and >= NVIEW
    prep_kernel<<<(nprep + 255) / 256, 256>>>(x, out);

    dim3 grid(NPAIR, NQ);
    fp_kernel<<<grid, 512>>>(out);
}

// round 10
// speedup vs baseline: 1.6890x; 1.0090x over previous
#include <cuda_runtime.h>
#include <cuda_fp16.h>
#include <math.h>

#define IMG     512
#define NVIEW   360
#define NPAIR   180          // view pairs (v, v+180): angles differ by exactly pi/2
#define NQ      16           // row-slices per view-pair (wave-quantization sweet spot)
#define RQ      (IMG / NQ)   // 32 rows per CTA
#define NSTAGE  (RQ / 2)
#define PW      516          // gmem line stride (entries 0..513 valid)
#define SPW     514          // smem line width
#define N1      (514 * PW)
#define OUTN    (2 * IMG * NVIEW)

// Interleaved fp16 dup-pair images, batch-interleaved, zeros baked into borders.
// Entry i of padded line p = ( I_lo, I_hi, J_lo, J_hi ) where each is half2(b0,b1),
// lo = pixel i-1, hi = pixel i, and J[r][c] = I[511-c][r] (90-deg rotation pairs
// view v with view v+180 whose angle differs by exactly pi/2).
__device__ uint4 g_ir[N1];   // row orientation
__device__ uint4 g_ic[N1];   // col orientation
__device__ float4 g_vp[NVIEW];
__device__ int    g_vmode[NVIEW];

__device__ __forceinline__ unsigned h2pix(const float* __restrict__ x, int y, int xx) {
    float2 f = make_float2(0.f, 0.f);
    if ((unsigned)y < 512u && (unsigned)xx < 512u) {
        f.x = x[y * IMG + xx];
        f.y = x[IMG * IMG + y * IMG + xx];
    }
    __half2 h = __float22half2_rn(f);
    return *reinterpret_cast<unsigned*>(&h);
}

__global__ void prep_kernel(const float* __restrict__ x, float* __restrict__ out) {
    int idx = blockIdx.x * blockDim.x + threadIdx.x;

    if (idx < NVIEW) {
        double ang = -M_PI * (double)(idx + 1) / (double)NVIEW - M_PI;
        float c = (float)cos(ang);
        float s = (float)sin(ang);
        if (fabsf(c) >= fabsf(s)) g_vp[idx] = make_float4(c, -s, s, c),  g_vmode[idx] = 0;
        else                      g_vp[idx] = make_float4(-s, c, c, s),  g_vmode[idx] = 1;
    }

    if (idx < OUTN) out[idx] = 0.0f;   // fp_kernel accumulates atomically

    if (idx < N1) {
        int p = idx / PW;
        int i = idx - p * PW;
        // row orientation: I part = image row p-1; J part = J row p-1 = I[512-i..][p-1]
        g_ir[idx] = make_uint4(h2pix(x, p - 1,   i - 1), h2pix(x, p - 1,   i),
                               h2pix(x, 512 - i, p - 1), h2pix(x, 511 - i, p - 1));
        // col orientation: I part = image col p-1; J part = J col p-1 = I[512-p][i-1..i]
        g_ic[idx] = make_uint4(h2pix(x, i - 1,   p - 1), h2pix(x, i,       p - 1),
                               h2pix(x, 512 - p, i - 1), h2pix(x, 512 - p, i));
    }
}

__device__ __forceinline__ void cand(const uint4* __restrict__ rowp,  // tile + 1
                                     float wp, float Q,
                                     float& a0, float& a1, float& a2, float& a3) {
    float Qc = fminf(fmaxf(Q, -1.0f), 512.0f);   // clamp lands on zero pads
    float q0 = floorf(Qc);
    float wq = Qc - q0;
    uint4 e = rowp[(int)q0];                     // one LDS.128: 4 pixels, both imgs+batches
    __half2 wqh = __float2half2_rn(wq);
    __half2 mI = __hfma2(wqh, __hsub2(*(const __half2*)&e.y, *(const __half2*)&e.x),
                         *(const __half2*)&e.x);
    __half2 mJ = __hfma2(wqh, __hsub2(*(const __half2*)&e.w, *(const __half2*)&e.z),
                         *(const __half2*)&e.z);
    float2 fI = __half22float2(mI);
    float2 fJ = __half22float2(mJ);
    a0 = fmaf(wp, fI.x, a0);
    a1 = fmaf(wp, fI.y, a1);
    a2 = fmaf(wp, fJ.x, a2);
    a3 = fmaf(wp, fJ.y, a3);
}

__global__ __launch_bounds__(512) void fp_kernel(float* __restrict__ out) {
    __shared__ uint4 sp[2][2][SPW];   // [buf][row-in-stage][entry], 32.9 KB

    int v = blockIdx.x;               // primary view; pair view = v + 180
    int q = blockIdx.y;
    int w = threadIdx.x;
    int r0 = q * RQ;

    float4 vp = g_vp[v];
    const uint4* __restrict__ G = g_vmode[v] ? g_ic : g_ir;

    float a    = vp.x;
    float bc   = vp.y;
    float absa = fabsf(a);
    float c2   = 1.0f - 2.0f * absa;            // for wp2
    float wr   = (float)w - 255.5f;
    float A    = fmaf(vp.z, wr, 255.5f);
    float B    = fmaf(vp.w, wr, 255.5f);
    float Bp   = fmaf(-255.5f, bc, B);          // Q = bc*hb + Bp
    float inv_a = 1.0f / a;

    float a0 = 0.f, a1 = 0.f, a2 = 0.f, a3 = 0.f;

    // hc at r = r0, advanced incrementally (drift << window margin)
    float hcv = fmaf((float)r0 - A, inv_a, 255.5f);

    // preload stage 0 (image rows r0, r0+1 -> padded lines r0+1, r0+2)
    {
        const uint4* s0 = G + (size_t)(r0 + 1) * PW;
        const uint4* s1 = G + (size_t)(r0 + 2) * PW;
        sp[0][0][w] = s0[w];
        sp[0][1][w] = s1[w];
        if (w < 2) { sp[0][0][512 + w] = s0[512 + w]; sp[0][1][512 + w] = s1[512 + w]; }
    }

    for (int st = 0; st < NSTAGE; st++) {
        __syncthreads();
        if (st + 1 < NSTAGE) {
            int nb = (st + 1) & 1;
            const uint4* s0 = G + (size_t)(r0 + 2 * st + 3) * PW;
            const uint4* s1 = G + (size_t)(r0 + 2 * st + 4) * PW;
            sp[nb][0][w] = s0[w];
            sp[nb][1][w] = s1[w];
            if (w < 2) { sp[nb][0][512 + w] = s0[512 + w]; sp[nb][1][512 + w] = s1[512 + w]; }
        }

        #pragma unroll
        for (int j = 0; j < 2; j++) {
            const uint4* rowp = &sp[st & 1][j][1];   // +1: index by (int)floor(Qc) in [-1,512]

            // hc solves P(h)=r; open support spans < 2*sqrt(2); 3 candidates
            // from hb = ceil(hc - 1.4146) provably cover it.
            float hb = ceilf(hcv - 1.4146f);
            int   h0 = (int)hb;
            float d  = hb - hcv;                  // in (-1.4146, -0.4146]
            float Q  = fmaf(bc, hb, Bp);

            float wp0 = fmaxf(fmaf( absa, d,               1.0f), 0.0f);  // d < 0
            float wp1 = fmaxf(fmaf(-absa, fabsf(d + 1.0f), 1.0f), 0.0f);
            float wp2 = fmaxf(fmaf(-absa, d,               c2),   0.0f);  // = 1-|a|(d+2)

            if ((unsigned)h0 > 509u) {            // rare edge rows
                if ((unsigned)h0       >= 512u) wp0 = 0.0f;
                if ((unsigned)(h0 + 1) >= 512u) wp1 = 0.0f;
                if ((unsigned)(h0 + 2) >= 512u) wp2 = 0.0f;
            }

            cand(rowp, wp0, Q,             a0, a1, a2, a3);
            cand(rowp, wp1, Q + bc,        a0, a1, a2, a3);
            cand(rowp, wp2, Q + 2.0f * bc, a0, a1, a2, a3);

            hcv += inv_a;
        }
    }

    int v2 = v + NPAIR;
    atomicAdd(&out[w * NVIEW + v],                a0 * 0.5f);
    atomicAdd(&out[IMG * NVIEW + w * NVIEW + v],  a1 * 0.5f);
    atomicAdd(&out[w * NVIEW + v2],               a2 * 0.5f);
    atomicAdd(&out[IMG * NVIEW + w * NVIEW + v2], a3 * 0.5f);
}

extern "C" void kernel_launch(void* const* d_in, const int* in_sizes, int n_in,
                              void* d_out, int out_size) {
    const float* x = (const float*)d_in[0];
    float* out = (float*)d_out;

    int nprep = OUTN;   // >= N1 and >= NVIEW
    prep_kernel<<<(nprep + 255) / 256, 256>>>(x, out);

    dim3 grid(NPAIR, NQ);
    fp_kernel<<<grid, 512>>>(out);
}